// round 2
// baseline (speedup 1.0000x reference)
#include <cuda_runtime.h>
#include <cstdint>
#include <cmath>

// ---------------- problem constants ----------------
#define Bv      8
#define NTOK    1024
#define Cdim    384
#define Hh      6
#define Dh      64
#define Mtok    1026            // N_TOK + CLS + pad
#define Ntok1   1025            // N_TOK + CLS
#define WWIN    256
#define HID     1536
#define SCALE   0.40824829046386307f   // 6^-0.5
#define EPSLN   1e-5f

// ---------------- scratch (static device globals; no allocation) ----------------
__device__ float g_h    [Bv * Mtok  * Cdim];     // LN1 output, padded
__device__ float g_qkv  [Bv * Mtok  * 3 * Cdim]; // qkv raw GEMM output
__device__ float g_attn [Bv * Ntok1 * Cdim];     // attention output (concat heads)
__device__ float g_h2   [Bv * Ntok1 * Cdim];     // proj + residual
__device__ float g_h2n  [Bv * Ntok1 * Cdim];     // LN2 output
__device__ float g_gath [Bv * WWIN  * 9 * Cdim]; // gathered pool input
__device__ float g_tok  [Bv * WWIN  * Cdim];     // pool output
__device__ float g_h3   [Bv * 257   * Cdim];     // concat
__device__ float g_h3n  [Bv * 257   * Cdim];     // LN3 output
__device__ float g_fc1  [Bv * 257   * HID];      // fc1+gelu output

// ---------------- helpers ----------------
__device__ __forceinline__ float block_reduce_sum128(float v, float* sh) {
    #pragma unroll
    for (int o = 16; o; o >>= 1) v += __shfl_xor_sync(0xffffffffu, v, o);
    int w = threadIdx.x >> 5;
    if ((threadIdx.x & 31) == 0) sh[w] = v;
    __syncthreads();
    v = sh[0] + sh[1] + sh[2] + sh[3];
    __syncthreads();
    return v;
}

// does an even window-center exist covering both a and b on one axis?
__device__ __forceinline__ bool axis_ok(int a, int b) {
    int lo = max(max(a, b) - 1, 0);
    int hi = min(min(a, b) + 1, 30);
    if (lo > hi) return false;
    return ((lo & 1) == 0) || (lo + 1 <= hi);
}

// ---------------- LN1 with zero-pad row ----------------
__global__ void ln1_pad_kernel(const float* __restrict__ x,
                               const float* __restrict__ w,
                               const float* __restrict__ b) {
    __shared__ float sh[4];
    int r = blockIdx.x;               // 0 .. Bv*Mtok-1
    int bb = r / Mtok, m = r % Mtok;
    int t = threadIdx.x;
    float* out = g_h + (size_t)r * Cdim;
    if (m == Ntok1) {                 // padded row -> zeros
        out[t] = 0.f; out[t + 128] = 0.f; out[t + 256] = 0.f;
        return;
    }
    const float* xr = x + ((size_t)bb * Ntok1 + m) * Cdim;
    float v0 = xr[t], v1 = xr[t + 128], v2 = xr[t + 256];
    float mu = block_reduce_sum128(v0 + v1 + v2, sh) * (1.f / Cdim);
    float d0 = v0 - mu, d1 = v1 - mu, d2 = v2 - mu;
    float var = block_reduce_sum128(d0 * d0 + d1 * d1 + d2 * d2, sh) * (1.f / Cdim);
    float rs = rsqrtf(var + EPSLN);
    out[t]       = d0 * rs * w[t]       + b[t];
    out[t + 128] = d1 * rs * w[t + 128] + b[t + 128];
    out[t + 256] = d2 * rs * w[t + 256] + b[t + 256];
}

// ---------------- generic LN (rows of width 384) ----------------
__global__ void ln_kernel(const float* __restrict__ in,
                          const float* __restrict__ w,
                          const float* __restrict__ b,
                          float* __restrict__ out) {
    __shared__ float sh[4];
    int r = blockIdx.x, t = threadIdx.x;
    const float* xr = in + (size_t)r * Cdim;
    float v0 = xr[t], v1 = xr[t + 128], v2 = xr[t + 256];
    float mu = block_reduce_sum128(v0 + v1 + v2, sh) * (1.f / Cdim);
    float d0 = v0 - mu, d1 = v1 - mu, d2 = v2 - mu;
    float var = block_reduce_sum128(d0 * d0 + d1 * d1 + d2 * d2, sh) * (1.f / Cdim);
    float rs = rsqrtf(var + EPSLN);
    float* o = out + (size_t)r * Cdim;
    o[t]       = d0 * rs * w[t]       + b[t];
    o[t + 128] = d1 * rs * w[t + 128] + b[t + 128];
    o[t + 256] = d2 * rs * w[t + 256] + b[t + 256];
}

// ---------------- SGEMM: C = A @ W^T (+bias) (+gelu) ----------------
// A: Mr x Kd row-major, W: Nc x Kd row-major, C: Mr x Nc row-major.
// Nc % 64 == 0, Kd % 16 == 0 guaranteed; Mr bounds-checked.
template <int ACT>
__global__ void __launch_bounds__(256)
sgemm_kernel(const float* __restrict__ A, const float* __restrict__ W,
             const float* __restrict__ bias, float* __restrict__ Cm,
             int Mr, int Nc, int Kd) {
    __shared__ float As[16 * 68];
    __shared__ float Bs[16 * 68];
    int tid = threadIdx.x;
    int tx = tid & 15, ty = tid >> 4;
    int m0 = blockIdx.y * 64, n0 = blockIdx.x * 64;
    int lrow = tid >> 2;            // 0..63
    int lk4  = (tid & 3) * 4;       // 0,4,8,12
    const float* Ap = A + (size_t)(m0 + lrow) * Kd + lk4;
    const float* Wp = W + (size_t)(n0 + lrow) * Kd + lk4;
    bool arow_ok = (m0 + lrow) < Mr;
    float acc[4][4] = {};
    for (int k0 = 0; k0 < Kd; k0 += 16) {
        float4 av = arow_ok ? *(const float4*)Ap : make_float4(0.f, 0.f, 0.f, 0.f);
        float4 wv = *(const float4*)Wp;
        Ap += 16; Wp += 16;
        __syncthreads();
        As[(lk4 + 0) * 68 + lrow] = av.x;
        As[(lk4 + 1) * 68 + lrow] = av.y;
        As[(lk4 + 2) * 68 + lrow] = av.z;
        As[(lk4 + 3) * 68 + lrow] = av.w;
        Bs[(lk4 + 0) * 68 + lrow] = wv.x;
        Bs[(lk4 + 1) * 68 + lrow] = wv.y;
        Bs[(lk4 + 2) * 68 + lrow] = wv.z;
        Bs[(lk4 + 3) * 68 + lrow] = wv.w;
        __syncthreads();
        #pragma unroll
        for (int kk = 0; kk < 16; kk++) {
            float4 a = *(const float4*)&As[kk * 68 + ty * 4];
            float4 bq = *(const float4*)&Bs[kk * 68 + tx * 4];
            acc[0][0] += a.x * bq.x; acc[0][1] += a.x * bq.y; acc[0][2] += a.x * bq.z; acc[0][3] += a.x * bq.w;
            acc[1][0] += a.y * bq.x; acc[1][1] += a.y * bq.y; acc[1][2] += a.y * bq.z; acc[1][3] += a.y * bq.w;
            acc[2][0] += a.z * bq.x; acc[2][1] += a.z * bq.y; acc[2][2] += a.z * bq.z; acc[2][3] += a.z * bq.w;
            acc[3][0] += a.w * bq.x; acc[3][1] += a.w * bq.y; acc[3][2] += a.w * bq.z; acc[3][3] += a.w * bq.w;
        }
    }
    int nbase = n0 + tx * 4;
    float b0 = 0.f, b1 = 0.f, b2 = 0.f, b3 = 0.f;
    if (bias) { b0 = bias[nbase]; b1 = bias[nbase + 1]; b2 = bias[nbase + 2]; b3 = bias[nbase + 3]; }
    #pragma unroll
    for (int i = 0; i < 4; i++) {
        int row = m0 + ty * 4 + i;
        if (row >= Mr) break;
        float4 v;
        v.x = acc[i][0] + b0; v.y = acc[i][1] + b1; v.z = acc[i][2] + b2; v.w = acc[i][3] + b3;
        if (ACT == 1) {
            v.x = 0.5f * v.x * (1.f + erff(v.x * 0.70710678118654752f));
            v.y = 0.5f * v.y * (1.f + erff(v.y * 0.70710678118654752f));
            v.z = 0.5f * v.z * (1.f + erff(v.z * 0.70710678118654752f));
            v.w = 0.5f * v.w * (1.f + erff(v.w * 0.70710678118654752f));
        }
        *(float4*)(Cm + (size_t)row * Nc + nbase) = v;
    }
}

// ---------------- sparse attention for image queries (m = 1..1024) ----------------
// grid: (1024, Bv), block: 192 (6 warps = 6 heads). qkv row layout: [q(384) k(384) v(384)].
__global__ void attn_sparse_kernel() {
    int m = blockIdx.x + 1;
    int b = blockIdx.y;
    int h = threadIdx.x >> 5;
    int lane = threadIdx.x & 31;
    const float* base = g_qkv + (size_t)b * Mtok * (3 * Cdim);
    const float* qrow = base + (size_t)m * (3 * Cdim) + h * Dh;
    float q0 = qrow[lane] * SCALE, q1 = qrow[lane + 32] * SCALE;
    float mx = -1e30f, l = 0.f, a0 = 0.f, a1 = 0.f;

    auto doKey = [&](int kidx) {
        const float* kr = base + (size_t)kidx * (3 * Cdim) + Cdim + h * Dh;
        float s = q0 * kr[lane] + q1 * kr[lane + 32];
        #pragma unroll
        for (int o = 16; o; o >>= 1) s += __shfl_xor_sync(0xffffffffu, s, o);
        float mn = fmaxf(mx, s);
        float corr = __expf(mx - mn);
        float p = __expf(s - mn);
        const float* vr = base + (size_t)kidx * (3 * Cdim) + 2 * Cdim + h * Dh;
        a0 = a0 * corr + p * vr[lane];
        a1 = a1 * corr + p * vr[lane + 32];
        l = l * corr + p;
        mx = mn;
    };

    doKey(0);  // CLS key: mask==1 -> real score
    int i = m - 1, r = i >> 5, c = i & 31;
    #pragma unroll
    for (int dr = -2; dr <= 2; dr++) {
        int rp = r + dr;
        if ((unsigned)rp >= 32u || !axis_ok(r, rp)) continue;
        #pragma unroll
        for (int dc = -2; dc <= 2; dc++) {
            int cp = c + dc;
            if ((unsigned)cp >= 32u || !axis_ok(c, cp)) continue;
            doKey(1 + rp * 32 + cp);
        }
    }
    // padded key 1025: mask==0 -> score 0, v == 0 (affects only denominator)
    {
        float s = 0.f;
        float mn = fmaxf(mx, s);
        float corr = __expf(mx - mn);
        float p = __expf(s - mn);
        a0 *= corr; a1 *= corr; l = l * corr + p;
    }
    float inv = 1.f / l;
    float* o = g_attn + ((size_t)(b * Ntok1 + m)) * Cdim + h * Dh;
    o[lane] = a0 * inv;
    o[lane + 32] = a1 * inv;
}

// ---------------- dense attention for the CLS query (m = 0) ----------------
// grid: (Hh, Bv), block: 256
__global__ void attn_cls_kernel() {
    __shared__ float sc[Mtok];
    __shared__ float qs[Dh];
    __shared__ float red[8];
    __shared__ float accsh[256];
    int h = blockIdx.x, b = blockIdx.y;
    int tid = threadIdx.x;
    const float* base = g_qkv + (size_t)b * Mtok * (3 * Cdim);
    if (tid < Dh) qs[tid] = base[h * Dh + tid] * SCALE;   // q of CLS
    __syncthreads();

    float lmax = -1e30f;
    for (int k = tid; k < Ntok1; k += 256) {
        const float* kr = base + (size_t)k * (3 * Cdim) + Cdim + h * Dh;
        float s = 0.f;
        #pragma unroll
        for (int d = 0; d < Dh; d++) s += qs[d] * kr[d];
        sc[k] = s;
        lmax = fmaxf(lmax, s);
    }
    if (tid == 0) sc[Ntok1] = 0.f;  // padded key: score 0
    lmax = fmaxf(lmax, 0.f);
    // block max
    #pragma unroll
    for (int o = 16; o; o >>= 1) lmax = fmaxf(lmax, __shfl_xor_sync(0xffffffffu, lmax, o));
    if ((tid & 31) == 0) red[tid >> 5] = lmax;
    __syncthreads();
    float mx = red[0];
    #pragma unroll
    for (int w = 1; w < 8; w++) mx = fmaxf(mx, red[w]);
    __syncthreads();

    float lsum = 0.f;
    for (int k = tid; k < Mtok; k += 256) {
        float p = __expf(sc[k] - mx);
        sc[k] = p;
        lsum += p;
    }
    #pragma unroll
    for (int o = 16; o; o >>= 1) lsum += __shfl_xor_sync(0xffffffffu, lsum, o);
    if ((tid & 31) == 0) red[tid >> 5] = lsum;
    __syncthreads();
    float Z = red[0] + red[1] + red[2] + red[3] + red[4] + red[5] + red[6] + red[7];

    // PV: 4 key-slices x 64 dims
    int d = tid & 63, ks = tid >> 6;
    float acc = 0.f;
    for (int k = ks; k < Ntok1; k += 4)    // v row 1025 is zero, skip
        acc += sc[k] * base[(size_t)k * (3 * Cdim) + 2 * Cdim + h * Dh + d];
    accsh[tid] = acc;
    __syncthreads();
    if (tid < 64) {
        float o = accsh[tid] + accsh[64 + tid] + accsh[128 + tid] + accsh[192 + tid];
        g_attn[((size_t)(b * Ntok1)) * Cdim + h * Dh + tid] = o / Z;
    }
}

// ---------------- proj residual add: g_h2 += g_h (row-skewed) ----------------
__global__ void resadd_kernel() {
    int idx = blockIdx.x * 256 + threadIdx.x;
    if (idx >= Bv * Ntok1 * Cdim) return;
    int r = idx / Cdim;
    int bb = r / Ntok1;
    g_h2[idx] += g_h[idx + (size_t)bb * Cdim];
}

// ---------------- window gather (analytic IDX_FLAT) ----------------
__global__ void gather_kernel() {
    int bw = blockIdx.x;              // b*256 + w
    int b = bw >> 8, w = bw & 255;
    int wy = w >> 4, wx = w & 15;
    int t = threadIdx.x;
    #pragma unroll
    for (int j = 0; j < 9; j++) {
        int dy = j / 3 - 1, dx = j % 3 - 1;
        int rp = 2 * wy + dy, cp = 2 * wx + dx;
        int g = (rp >= 0 && rp < 32 && cp >= 0 && cp < 32) ? (1 + rp * 32 + cp) : 1024;
        const float* src = g_h2n + ((size_t)b * Ntok1 + g) * Cdim;
        float* dst = g_gath + (size_t)bw * (9 * Cdim) + j * Cdim;
        for (int c = t; c < Cdim; c += 128) dst[c] = src[c];
    }
}

// ---------------- concat [h2n[:, :1], tok] ----------------
__global__ void concat_kernel() {
    int idx = blockIdx.x * 256 + threadIdx.x;
    if (idx >= Bv * 257 * Cdim) return;
    int r = idx / Cdim, c = idx % Cdim;
    int b = r / 257, t = r % 257;
    float v = (t == 0) ? g_h2n[((size_t)b * Ntok1) * Cdim + c]
                       : g_tok[((size_t)(b * WWIN + (t - 1))) * Cdim + c];
    g_h3[idx] = v;
}

// ---------------- launch ----------------
extern "C" void kernel_launch(void* const* d_in, const int* in_sizes, int n_in,
                              void* d_out, int out_size) {
    const float* x       = (const float*)d_in[0];
    const float* norm1_w = (const float*)d_in[1];
    const float* norm1_b = (const float*)d_in[2];
    const float* qkv_w   = (const float*)d_in[3];
    const float* proj_w  = (const float*)d_in[4];
    const float* proj_b  = (const float*)d_in[5];
    const float* norm2_w = (const float*)d_in[6];
    const float* norm2_b = (const float*)d_in[7];
    const float* pool_w  = (const float*)d_in[8];
    const float* pool_b  = (const float*)d_in[9];
    const float* norm3_w = (const float*)d_in[10];
    const float* norm3_b = (const float*)d_in[11];
    const float* fc1_w   = (const float*)d_in[12];
    const float* fc1_b   = (const float*)d_in[13];
    const float* fc2_w   = (const float*)d_in[14];
    const float* fc2_b   = (const float*)d_in[15];
    float* out = (float*)d_out;

    float *p_h, *p_qkv, *p_attn, *p_h2, *p_h2n, *p_gath, *p_tok, *p_h3, *p_h3n, *p_fc1;
    cudaGetSymbolAddress((void**)&p_h,    g_h);
    cudaGetSymbolAddress((void**)&p_qkv,  g_qkv);
    cudaGetSymbolAddress((void**)&p_attn, g_attn);
    cudaGetSymbolAddress((void**)&p_h2,   g_h2);
    cudaGetSymbolAddress((void**)&p_h2n,  g_h2n);
    cudaGetSymbolAddress((void**)&p_gath, g_gath);
    cudaGetSymbolAddress((void**)&p_tok,  g_tok);
    cudaGetSymbolAddress((void**)&p_h3,   g_h3);
    cudaGetSymbolAddress((void**)&p_h3n,  g_h3n);
    cudaGetSymbolAddress((void**)&p_fc1,  g_fc1);

    // 1) LN1 + zero-pad
    ln1_pad_kernel<<<Bv * Mtok, 128>>>(x, norm1_w, norm1_b);
    // 2) QKV GEMM: (8208 x 384) @ (384 x 1152)
    sgemm_kernel<0><<<dim3(1152 / 64, (Bv * Mtok + 63) / 64), 256>>>(
        p_h, qkv_w, nullptr, p_qkv, Bv * Mtok, 3 * Cdim, Cdim);
    // 3) attention
    attn_cls_kernel<<<dim3(Hh, Bv), 256>>>();
    attn_sparse_kernel<<<dim3(NTOK, Bv), 192>>>();
    // 4) proj GEMM + residual
    sgemm_kernel<0><<<dim3(Cdim / 64, (Bv * Ntok1 + 63) / 64), 256>>>(
        p_attn, proj_w, proj_b, p_h2, Bv * Ntok1, Cdim, Cdim);
    resadd_kernel<<<(Bv * Ntok1 * Cdim + 255) / 256, 256>>>();
    // 5) LN2
    ln_kernel<<<Bv * Ntok1, 128>>>(p_h2, norm2_w, norm2_b, p_h2n);
    // 6) gather + pool GEMM: (2048 x 3456) @ (3456 x 384)
    gather_kernel<<<Bv * WWIN, 128>>>();
    sgemm_kernel<0><<<dim3(Cdim / 64, (Bv * WWIN + 63) / 64), 256>>>(
        p_gath, pool_w, pool_b, p_tok, Bv * WWIN, Cdim, 9 * Cdim);
    // 7) concat + LN3
    concat_kernel<<<(Bv * 257 * Cdim + 255) / 256, 256>>>();
    ln_kernel<<<Bv * 257, 128>>>(p_h3, norm3_w, norm3_b, p_h3n);
    // 8) MLP
    sgemm_kernel<1><<<dim3(HID / 64, (Bv * 257 + 63) / 64), 256>>>(
        p_h3n, fc1_w, fc1_b, p_fc1, Bv * 257, HID, Cdim);
    sgemm_kernel<0><<<dim3(Cdim / 64, (Bv * 257 + 63) / 64), 256>>>(
        p_fc1, fc2_w, fc2_b, out, Bv * 257, Cdim, HID);
}

// round 12
// speedup vs baseline: 2.0157x; 2.0157x over previous
#include <cuda_runtime.h>
#include <cstdint>
#include <cmath>

// ---------------- problem constants ----------------
#define Bv      8
#define NTOK    1024
#define Cdim    384
#define Hh      6
#define Dh      64
#define Mtok    1026            // N_TOK + CLS + pad
#define Ntok1   1025            // N_TOK + CLS
#define WWIN    256
#define HID     1536
#define SCALE   0.40824829046386307f   // 6^-0.5
#define EPSLN   1e-5f

// ---------------- scratch (static device globals; no allocation) ----------------
__device__ float g_h    [Bv * Mtok  * Cdim];
__device__ float g_qkv  [Bv * Mtok  * 3 * Cdim];
__device__ float g_attn [Bv * Ntok1 * Cdim];
__device__ float g_h2   [Bv * Ntok1 * Cdim];
__device__ float g_h2n  [Bv * Ntok1 * Cdim];
__device__ float g_gath [Bv * WWIN  * 9 * Cdim];
__device__ float g_tok  [Bv * WWIN  * Cdim];
__device__ float g_h3   [Bv * 257   * Cdim];
__device__ float g_h3n  [Bv * 257   * Cdim];
__device__ float g_fc1  [Bv * 257   * HID];

// ---------------- tf32 helpers (sm_80+ features; safe under compute_103) ----------------
__device__ __forceinline__ float to_tf32(float x) {
    float y; asm("cvt.rna.tf32.f32 %0, %1;" : "=f"(y) : "f"(x)); return y;
}
__device__ __forceinline__ void mma_tf32(float* c, const uint32_t* a, const uint32_t* b) {
    asm volatile(
        "mma.sync.aligned.m16n8k8.row.col.f32.tf32.tf32.f32 "
        "{%0,%1,%2,%3}, {%4,%5,%6,%7}, {%8,%9}, {%0,%1,%2,%3};"
        : "+f"(c[0]), "+f"(c[1]), "+f"(c[2]), "+f"(c[3])
        : "r"(a[0]), "r"(a[1]), "r"(a[2]), "r"(a[3]), "r"(b[0]), "r"(b[1]));
}

// ============ tf32 mma.sync GEMM: C = A @ W^T (+bias)(+gelu) ============
// A: Mr x Kd row-major fp32. W: Nc x Kd row-major fp32.
// Kd % 32 == 0, Nc % 128 == 0. Block tile 128x128, 8 warps (2m x 4n),
// warp tile 64x32 (4x4 m16n8k8 atoms). K-panel = 32, double-buffered smem.
#define SSTR 36                       // smem row stride in floats (conflict-free, 16B-aligned)
#define PANEL_F (128 * SSTR)          // floats per (A or B) buffer

template <int ACT>
__global__ void __launch_bounds__(256)
gemm_mma(const float* __restrict__ A, const float* __restrict__ W,
         const float* __restrict__ bias, float* __restrict__ Cm,
         int Mr, int Nc, int Kd) {
    extern __shared__ __align__(16) float smem[];
    // layout: A0 A1 B0 B1, each PANEL_F floats
    const int tid = threadIdx.x;
    const int wid = tid >> 5, lane = tid & 31;
    const int g = lane >> 2, t = lane & 3;        // mma group / thread-in-group
    const int wm = wid & 1, wn = wid >> 1;        // 2 m-warps x 4 n-warps
    const int m0 = blockIdx.y * 128, n0 = blockIdx.x * 128;

    const int ldrow = tid >> 3;                   // 0..31 (x4 iters -> 128 rows)
    const int ldq   = tid & 7;                    // float4 index within 32-float panel row

    float acc[4][4][4];
    #pragma unroll
    for (int i = 0; i < 4; i++)
        #pragma unroll
        for (int j = 0; j < 4; j++)
            #pragma unroll
            for (int k = 0; k < 4; k++) acc[i][j][k] = 0.f;

    const int P = Kd >> 5;                        // K-panels of 32
    float4 ra[4], rb[4];

    auto ldg = [&](int p) {
        #pragma unroll
        for (int k = 0; k < 4; k++) {
            int row = ldrow + 32 * k;
            int gr = m0 + row;
            ra[k] = (gr < Mr) ? *(const float4*)(A + (size_t)gr * Kd + p * 32 + ldq * 4)
                              : make_float4(0.f, 0.f, 0.f, 0.f);
            rb[k] = *(const float4*)(W + (size_t)(n0 + row) * Kd + p * 32 + ldq * 4);
        }
    };
    auto sts = [&](int b) {
        float* Ab = smem + b * PANEL_F;
        float* Bb = smem + 2 * PANEL_F + b * PANEL_F;
        #pragma unroll
        for (int k = 0; k < 4; k++) {
            int row = ldrow + 32 * k;
            float4 va = ra[k], vb = rb[k];
            va.x = to_tf32(va.x); va.y = to_tf32(va.y); va.z = to_tf32(va.z); va.w = to_tf32(va.w);
            vb.x = to_tf32(vb.x); vb.y = to_tf32(vb.y); vb.z = to_tf32(vb.z); vb.w = to_tf32(vb.w);
            *(float4*)(Ab + row * SSTR + ldq * 4) = va;
            *(float4*)(Bb + row * SSTR + ldq * 4) = vb;
        }
    };
    auto compute = [&](int b) {
        const float* Ab = smem + b * PANEL_F;
        const float* Bb = smem + 2 * PANEL_F + b * PANEL_F;
        #pragma unroll
        for (int kk = 0; kk < 4; kk++) {          // 4 x k8 steps = K panel 32
            uint32_t af[4][4];
            #pragma unroll
            for (int ma = 0; ma < 4; ma++) {
                const float* p = Ab + (wm * 64 + ma * 16 + g) * SSTR + kk * 8 + t;
                af[ma][0] = __float_as_uint(p[0]);
                af[ma][1] = __float_as_uint(p[8 * SSTR]);
                af[ma][2] = __float_as_uint(p[4]);
                af[ma][3] = __float_as_uint(p[8 * SSTR + 4]);
            }
            uint32_t bf[4][2];
            #pragma unroll
            for (int na = 0; na < 4; na++) {
                const float* p = Bb + (wn * 32 + na * 8 + g) * SSTR + kk * 8 + t;
                bf[na][0] = __float_as_uint(p[0]);
                bf[na][1] = __float_as_uint(p[4]);
            }
            #pragma unroll
            for (int ma = 0; ma < 4; ma++)
                #pragma unroll
                for (int na = 0; na < 4; na++)
                    mma_tf32(acc[ma][na], af[ma], bf[na]);
        }
    };

    ldg(0);
    sts(0);
    __syncthreads();
    for (int p = 0; p < P; p++) {
        int b = p & 1;
        if (p + 1 < P) ldg(p + 1);
        compute(b);
        __syncthreads();
        if (p + 1 < P) { sts(b ^ 1); __syncthreads(); }
    }

    // ---- epilogue: accum regs -> global (+bias/gelu), float2 stores ----
    #pragma unroll
    for (int ma = 0; ma < 4; ma++) {
        int row = m0 + wm * 64 + ma * 16 + g;
        #pragma unroll
        for (int na = 0; na < 4; na++) {
            int col = n0 + wn * 32 + na * 8 + 2 * t;
            float b0 = 0.f, b1 = 0.f;
            if (bias) { b0 = bias[col]; b1 = bias[col + 1]; }
            float v0 = acc[ma][na][0] + b0, v1 = acc[ma][na][1] + b1;
            float v2 = acc[ma][na][2] + b0, v3 = acc[ma][na][3] + b1;
            if (ACT) {
                v0 = 0.5f * v0 * (1.f + erff(v0 * 0.70710678118654752f));
                v1 = 0.5f * v1 * (1.f + erff(v1 * 0.70710678118654752f));
                v2 = 0.5f * v2 * (1.f + erff(v2 * 0.70710678118654752f));
                v3 = 0.5f * v3 * (1.f + erff(v3 * 0.70710678118654752f));
            }
            if (row < Mr)     *(float2*)(Cm + (size_t)row * Nc + col)       = make_float2(v0, v1);
            if (row + 8 < Mr) *(float2*)(Cm + (size_t)(row + 8) * Nc + col) = make_float2(v2, v3);
        }
    }
}

// ---------------- block reduce helper ----------------
__device__ __forceinline__ float block_reduce_sum128(float v, float* sh) {
    #pragma unroll
    for (int o = 16; o; o >>= 1) v += __shfl_xor_sync(0xffffffffu, v, o);
    int w = threadIdx.x >> 5;
    if ((threadIdx.x & 31) == 0) sh[w] = v;
    __syncthreads();
    v = sh[0] + sh[1] + sh[2] + sh[3];
    __syncthreads();
    return v;
}

__device__ __forceinline__ bool axis_ok(int a, int b) {
    int lo = max(max(a, b) - 1, 0);
    int hi = min(min(a, b) + 1, 30);
    if (lo > hi) return false;
    return ((lo & 1) == 0) || (lo + 1 <= hi);
}

// ---------------- LN1 with zero-pad row ----------------
__global__ void ln1_pad_kernel(const float* __restrict__ x,
                               const float* __restrict__ w,
                               const float* __restrict__ b) {
    __shared__ float sh[4];
    int r = blockIdx.x;
    int bb = r / Mtok, m = r % Mtok;
    int t = threadIdx.x;
    float* out = g_h + (size_t)r * Cdim;
    if (m == Ntok1) {
        out[t] = 0.f; out[t + 128] = 0.f; out[t + 256] = 0.f;
        return;
    }
    const float* xr = x + ((size_t)bb * Ntok1 + m) * Cdim;
    float v0 = xr[t], v1 = xr[t + 128], v2 = xr[t + 256];
    float mu = block_reduce_sum128(v0 + v1 + v2, sh) * (1.f / Cdim);
    float d0 = v0 - mu, d1 = v1 - mu, d2 = v2 - mu;
    float var = block_reduce_sum128(d0 * d0 + d1 * d1 + d2 * d2, sh) * (1.f / Cdim);
    float rs = rsqrtf(var + EPSLN);
    out[t]       = d0 * rs * w[t]       + b[t];
    out[t + 128] = d1 * rs * w[t + 128] + b[t + 128];
    out[t + 256] = d2 * rs * w[t + 256] + b[t + 256];
}

// ---------------- generic LN ----------------
__global__ void ln_kernel(const float* __restrict__ in,
                          const float* __restrict__ w,
                          const float* __restrict__ b,
                          float* __restrict__ out) {
    __shared__ float sh[4];
    int r = blockIdx.x, t = threadIdx.x;
    const float* xr = in + (size_t)r * Cdim;
    float v0 = xr[t], v1 = xr[t + 128], v2 = xr[t + 256];
    float mu = block_reduce_sum128(v0 + v1 + v2, sh) * (1.f / Cdim);
    float d0 = v0 - mu, d1 = v1 - mu, d2 = v2 - mu;
    float var = block_reduce_sum128(d0 * d0 + d1 * d1 + d2 * d2, sh) * (1.f / Cdim);
    float rs = rsqrtf(var + EPSLN);
    float* o = out + (size_t)r * Cdim;
    o[t]       = d0 * rs * w[t]       + b[t];
    o[t + 128] = d1 * rs * w[t + 128] + b[t + 128];
    o[t + 256] = d2 * rs * w[t + 256] + b[t + 256];
}

// ---------------- sparse attention (image queries) ----------------
__global__ void attn_sparse_kernel() {
    int m = blockIdx.x + 1;
    int b = blockIdx.y;
    int h = threadIdx.x >> 5;
    int lane = threadIdx.x & 31;
    const float* base = g_qkv + (size_t)b * Mtok * (3 * Cdim);
    const float* qrow = base + (size_t)m * (3 * Cdim) + h * Dh;
    float q0 = qrow[lane] * SCALE, q1 = qrow[lane + 32] * SCALE;
    float mx = -1e30f, l = 0.f, a0 = 0.f, a1 = 0.f;

    auto doKey = [&](int kidx) {
        const float* kr = base + (size_t)kidx * (3 * Cdim) + Cdim + h * Dh;
        float s = q0 * kr[lane] + q1 * kr[lane + 32];
        #pragma unroll
        for (int o = 16; o; o >>= 1) s += __shfl_xor_sync(0xffffffffu, s, o);
        float mn = fmaxf(mx, s);
        float corr = __expf(mx - mn);
        float p = __expf(s - mn);
        const float* vr = base + (size_t)kidx * (3 * Cdim) + 2 * Cdim + h * Dh;
        a0 = a0 * corr + p * vr[lane];
        a1 = a1 * corr + p * vr[lane + 32];
        l = l * corr + p;
        mx = mn;
    };

    doKey(0);
    int i = m - 1, r = i >> 5, c = i & 31;
    #pragma unroll
    for (int dr = -2; dr <= 2; dr++) {
        int rp = r + dr;
        if ((unsigned)rp >= 32u || !axis_ok(r, rp)) continue;
        #pragma unroll
        for (int dc = -2; dc <= 2; dc++) {
            int cp = c + dc;
            if ((unsigned)cp >= 32u || !axis_ok(c, cp)) continue;
            doKey(1 + rp * 32 + cp);
        }
    }
    {   // padded key: score 0, v == 0
        float mn = fmaxf(mx, 0.f);
        float corr = __expf(mx - mn);
        float p = __expf(0.f - mn);
        a0 *= corr; a1 *= corr; l = l * corr + p;
    }
    float inv = 1.f / l;
    float* o = g_attn + ((size_t)(b * Ntok1 + m)) * Cdim + h * Dh;
    o[lane] = a0 * inv;
    o[lane + 32] = a1 * inv;
}

// ---------------- dense attention for CLS query ----------------
__global__ void attn_cls_kernel() {
    __shared__ float sc[Mtok];
    __shared__ float qs[Dh];
    __shared__ float red[8];
    __shared__ float accsh[256];
    int h = blockIdx.x, b = blockIdx.y;
    int tid = threadIdx.x;
    const float* base = g_qkv + (size_t)b * Mtok * (3 * Cdim);
    if (tid < Dh) qs[tid] = base[h * Dh + tid] * SCALE;
    __syncthreads();

    float lmax = -1e30f;
    for (int k = tid; k < Ntok1; k += 256) {
        const float* kr = base + (size_t)k * (3 * Cdim) + Cdim + h * Dh;
        float s = 0.f;
        #pragma unroll
        for (int d = 0; d < Dh; d++) s += qs[d] * kr[d];
        sc[k] = s;
        lmax = fmaxf(lmax, s);
    }
    if (tid == 0) sc[Ntok1] = 0.f;
    lmax = fmaxf(lmax, 0.f);
    #pragma unroll
    for (int o = 16; o; o >>= 1) lmax = fmaxf(lmax, __shfl_xor_sync(0xffffffffu, lmax, o));
    if ((tid & 31) == 0) red[tid >> 5] = lmax;
    __syncthreads();
    float mx = red[0];
    #pragma unroll
    for (int w = 1; w < 8; w++) mx = fmaxf(mx, red[w]);
    __syncthreads();

    float lsum = 0.f;
    for (int k = tid; k < Mtok; k += 256) {
        float p = __expf(sc[k] - mx);
        sc[k] = p;
        lsum += p;
    }
    #pragma unroll
    for (int o = 16; o; o >>= 1) lsum += __shfl_xor_sync(0xffffffffu, lsum, o);
    if ((tid & 31) == 0) red[tid >> 5] = lsum;
    __syncthreads();
    float Z = red[0] + red[1] + red[2] + red[3] + red[4] + red[5] + red[6] + red[7];

    int d = tid & 63, ks = tid >> 6;
    float acc = 0.f;
    for (int k = ks; k < Ntok1; k += 4)
        acc += sc[k] * base[(size_t)k * (3 * Cdim) + 2 * Cdim + h * Dh + d];
    accsh[tid] = acc;
    __syncthreads();
    if (tid < 64) {
        float o = accsh[tid] + accsh[64 + tid] + accsh[128 + tid] + accsh[192 + tid];
        g_attn[((size_t)(b * Ntok1)) * Cdim + h * Dh + tid] = o / Z;
    }
}

// ---------------- residual add ----------------
__global__ void resadd_kernel() {
    int idx = blockIdx.x * 256 + threadIdx.x;
    if (idx >= Bv * Ntok1 * Cdim) return;
    int r = idx / Cdim;
    int bb = r / Ntok1;
    g_h2[idx] += g_h[idx + (size_t)bb * Cdim];
}

// ---------------- window gather ----------------
__global__ void gather_kernel() {
    int bw = blockIdx.x;
    int b = bw >> 8, w = bw & 255;
    int wy = w >> 4, wx = w & 15;
    int t = threadIdx.x;
    #pragma unroll
    for (int j = 0; j < 9; j++) {
        int dy = j / 3 - 1, dx = j % 3 - 1;
        int rp = 2 * wy + dy, cp = 2 * wx + dx;
        int g = (rp >= 0 && rp < 32 && cp >= 0 && cp < 32) ? (1 + rp * 32 + cp) : 1024;
        const float* src = g_h2n + ((size_t)b * Ntok1 + g) * Cdim;
        float* dst = g_gath + (size_t)bw * (9 * Cdim) + j * Cdim;
        for (int c = t; c < Cdim; c += 128) dst[c] = src[c];
    }
}

// ---------------- concat ----------------
__global__ void concat_kernel() {
    int idx = blockIdx.x * 256 + threadIdx.x;
    if (idx >= Bv * 257 * Cdim) return;
    int r = idx / Cdim, c = idx % Cdim;
    int b = r / 257, t = r % 257;
    float v = (t == 0) ? g_h2n[((size_t)b * Ntok1) * Cdim + c]
                       : g_tok[((size_t)(b * WWIN + (t - 1))) * Cdim + c];
    g_h3[idx] = v;
}

// ---------------- launch ----------------
extern "C" void kernel_launch(void* const* d_in, const int* in_sizes, int n_in,
                              void* d_out, int out_size) {
    const float* x       = (const float*)d_in[0];
    const float* norm1_w = (const float*)d_in[1];
    const float* norm1_b = (const float*)d_in[2];
    const float* qkv_w   = (const float*)d_in[3];
    const float* proj_w  = (const float*)d_in[4];
    const float* proj_b  = (const float*)d_in[5];
    const float* norm2_w = (const float*)d_in[6];
    const float* norm2_b = (const float*)d_in[7];
    const float* pool_w  = (const float*)d_in[8];
    const float* pool_b  = (const float*)d_in[9];
    const float* norm3_w = (const float*)d_in[10];
    const float* norm3_b = (const float*)d_in[11];
    const float* fc1_w   = (const float*)d_in[12];
    const float* fc1_b   = (const float*)d_in[13];
    const float* fc2_w   = (const float*)d_in[14];
    const float* fc2_b   = (const float*)d_in[15];
    float* out = (float*)d_out;

    float *p_h, *p_qkv, *p_attn, *p_h2, *p_h2n, *p_gath, *p_tok, *p_h3, *p_h3n, *p_fc1;
    cudaGetSymbolAddress((void**)&p_h,    g_h);
    cudaGetSymbolAddress((void**)&p_qkv,  g_qkv);
    cudaGetSymbolAddress((void**)&p_attn, g_attn);
    cudaGetSymbolAddress((void**)&p_h2,   g_h2);
    cudaGetSymbolAddress((void**)&p_h2n,  g_h2n);
    cudaGetSymbolAddress((void**)&p_gath, g_gath);
    cudaGetSymbolAddress((void**)&p_tok,  g_tok);
    cudaGetSymbolAddress((void**)&p_h3,   g_h3);
    cudaGetSymbolAddress((void**)&p_h3n,  g_h3n);
    cudaGetSymbolAddress((void**)&p_fc1,  g_fc1);

    const int SMEMB = 4 * PANEL_F * sizeof(float);   // 73728 B (A0 A1 B0 B1)
    cudaFuncSetAttribute(gemm_mma<0>, cudaFuncAttributeMaxDynamicSharedMemorySize, SMEMB);
    cudaFuncSetAttribute(gemm_mma<1>, cudaFuncAttributeMaxDynamicSharedMemorySize, SMEMB);

    // 1) LN1 + zero-pad
    ln1_pad_kernel<<<Bv * Mtok, 128>>>(x, norm1_w, norm1_b);
    // 2) QKV GEMM: (8208 x 384) @ (384 x 1152)
    gemm_mma<0><<<dim3(1152 / 128, (Bv * Mtok + 127) / 128), 256, SMEMB>>>(
        p_h, qkv_w, nullptr, p_qkv, Bv * Mtok, 3 * Cdim, Cdim);
    // 3) attention
    attn_cls_kernel<<<dim3(Hh, Bv), 256>>>();
    attn_sparse_kernel<<<dim3(NTOK, Bv), 192>>>();
    // 4) proj GEMM + residual
    gemm_mma<0><<<dim3(Cdim / 128, (Bv * Ntok1 + 127) / 128), 256, SMEMB>>>(
        p_attn, proj_w, proj_b, p_h2, Bv * Ntok1, Cdim, Cdim);
    resadd_kernel<<<(Bv * Ntok1 * Cdim + 255) / 256, 256>>>();
    // 5) LN2
    ln_kernel<<<Bv * Ntok1, 128>>>(p_h2, norm2_w, norm2_b, p_h2n);
    // 6) gather + pool GEMM: (2048 x 3456) @ (3456 x 384)
    gather_kernel<<<Bv * WWIN, 128>>>();
    gemm_mma<0><<<dim3(Cdim / 128, (Bv * WWIN + 127) / 128), 256, SMEMB>>>(
        p_gath, pool_w, pool_b, p_tok, Bv * WWIN, Cdim, 9 * Cdim);
    // 7) concat + LN3
    concat_kernel<<<(Bv * 257 * Cdim + 255) / 256, 256>>>();
    ln_kernel<<<Bv * 257, 128>>>(p_h3, norm3_w, norm3_b, p_h3n);
    // 8) MLP
    gemm_mma<1><<<dim3(HID / 128, (Bv * 257 + 127) / 128), 256, SMEMB>>>(
        p_h3n, fc1_w, fc1_b, p_fc1, Bv * 257, HID, Cdim);
    gemm_mma<0><<<dim3(Cdim / 128, (Bv * 257 + 127) / 128), 256, SMEMB>>>(
        p_fc1, fc2_w, fc2_b, out, Bv * 257, Cdim, HID);
}